// round 11
// baseline (speedup 1.0000x reference)
#include <cuda_runtime.h>
#include <cuda_fp16.h>
#include <cstdint>

#define E_ 11
#define B_ 1024
#define D_ 1536
#define H_ 3072
#define C_ 5242

#define BM 128
#define BN 128
#define BK 16
#define NTHREADS 256
#define MT 2

#define SAS 24                    // A fp16 tile stride (halves)
#define SA_B (BM * SAS * 2)       // 6144 B per A fp16 stage
#define FAS 20                    // A fp32 staging stride (floats) [L1 kernel]
#define ASTG_B (BM * FAS * 4)     // 10240 B per A fp32 stage
#define FBS 132                   // B fp32 staging stride (floats) [L1 kernel]
#define BSTG_B (BK * FBS * 4)     // 8448 B per B fp32 stage
#define SBS 136                   // B fp16 tile stride (halves)
#define B16_B (BK * SBS * 2)      // 4352 B per B fp16 tile

// ---- scratch (device globals: no allocations allowed) ----
__device__ int    g_cnt[E_];
__device__ int    g_idx[E_ * B_];
__device__ __half g_h1[(size_t)B_ * H_];
__device__ __half g_h2[(size_t)B_ * H_];

// ---------------------------------------------------------------------------
__global__ void route_kernel(const float* __restrict__ mf) {
    int tid = threadIdx.x;
    if (tid < E_) g_cnt[tid] = 0;
    __syncthreads();
    float t = 1.0f - mf[tid];
    float q = t / 0.1f;               // IEEE div, matches XLA lowering
    int bin = (int)q;                 // trunc toward zero == astype(int32)
    bin = max(0, min(E_ - 1, bin));
    int pos = atomicAdd(&g_cnt[bin], 1);
    g_idx[bin * B_ + pos] = tid;
}

// ---- PTX helpers ----------------------------------------------------------
__device__ __forceinline__ void cp_async16(uint32_t s, const void* g) {
    asm volatile("cp.async.cg.shared.global [%0], [%1], 16;\n" :: "r"(s), "l"(g));
}
__device__ __forceinline__ void cp_commit() {
    asm volatile("cp.async.commit_group;\n" ::: "memory");
}
template <int N>
__device__ __forceinline__ void cp_wait() {
    asm volatile("cp.async.wait_group %0;\n" :: "n"(N) : "memory");
}
__device__ __forceinline__ void ldsm4(uint32_t r[4], uint32_t addr) {
    asm volatile("ldmatrix.sync.aligned.m8n8.x4.shared.b16 {%0,%1,%2,%3}, [%4];"
                 : "=r"(r[0]), "=r"(r[1]), "=r"(r[2]), "=r"(r[3]) : "r"(addr));
}
__device__ __forceinline__ void ldsm4t(uint32_t r[4], uint32_t addr) {
    asm volatile("ldmatrix.sync.aligned.m8n8.x4.trans.shared.b16 {%0,%1,%2,%3}, [%4];"
                 : "=r"(r[0]), "=r"(r[1]), "=r"(r[2]), "=r"(r[3]) : "r"(addr));
}
__device__ __forceinline__ void mma_f16(float c[4], const uint32_t a[4],
                                        const uint32_t b0, const uint32_t b1) {
    asm volatile(
        "mma.sync.aligned.m16n8k16.row.col.f32.f16.f16.f32 "
        "{%0,%1,%2,%3}, {%4,%5,%6,%7}, {%8,%9}, {%0,%1,%2,%3};\n"
        : "+f"(c[0]), "+f"(c[1]), "+f"(c[2]), "+f"(c[3])
        : "r"(a[0]), "r"(a[1]), "r"(a[2]), "r"(a[3]), "r"(b0), "r"(b1));
}
__device__ __forceinline__ void lds128f(float4& v, uint32_t a) {
    asm volatile("ld.shared.v4.f32 {%0,%1,%2,%3}, [%4];"
                 : "=f"(v.x), "=f"(v.y), "=f"(v.z), "=f"(v.w) : "r"(a));
}
__device__ __forceinline__ void sts128(uint32_t a, uint32_t v0, uint32_t v1,
                                       uint32_t v2, uint32_t v3) {
    asm volatile("st.shared.v4.b32 [%0], {%1,%2,%3,%4};\n"
                 :: "r"(a), "r"(v0), "r"(v1), "r"(v2), "r"(v3));
}
__device__ __forceinline__ uint32_t pack2(float x, float y) {
    __half2 h = __float22half2_rn(make_float2(x, y));
    return *reinterpret_cast<uint32_t*>(&h);
}
__device__ __forceinline__ float gelu_exact(float x) {
    return 0.5f * x * (1.0f + erff(x * 0.70710678118654752f));
}

// ===========================================================================
// Kernel A (L2/L3): A fp16 via 5-stage cp.async; B fp32 LDG -> reg cvt ->
// STS fp16. LDG issued at iteration top, consumed by STS only AFTER the MMA
// block (true 1.3-iteration scoreboard distance). CTA 128x128, 8 warps
// (64x32 tiles), 2 CTAs/SM.
// ===========================================================================
template <bool DO_GELU, bool OUT_HALF, bool ALIGN16>
__global__ void __launch_bounds__(NTHREADS, 2)
expert_gemm_reg(const __half* __restrict__ A, int lda,
                const float* __restrict__ W, const float* __restrict__ bias,
                void* __restrict__ Coutv, int ldc, int K, int N)
{
    const int e = blockIdx.z;
    const int cnt = g_cnt[e];
    const int mtile = blockIdx.y;
    if (mtile * BM >= cnt) return;
    const int n0 = blockIdx.x * BN;

    const int* idxE = g_idx + e * B_;
    const float* We = W + (size_t)e * K * N;
    const float* be = bias + (size_t)e * N;

    constexpr uint32_t OFF_A16 = 0;                 // 5 stages
    constexpr uint32_t OFF_B16 = 5 * SA_B;          // 2 tiles

    extern __shared__ char smem_raw[];
    const uint32_t s0 = (uint32_t)__cvta_generic_to_shared(smem_raw);

    const int tid = threadIdx.x;
    const int lane = tid & 31;
    const int warp = tid >> 5;

    // A: one gathered row per thread-pair
    const int rA = tid >> 1;
    const int ha = tid & 1;
    int gm = mtile * BM + rA;
    int gmc = gm < cnt ? gm : cnt - 1;
    const __half* a_h = A + (size_t)idxE[gmc] * lda + 8 * ha;
    const uint32_t a16_dst = s0 + OFF_A16 + (uint32_t)((rA * SAS + 8 * ha) * 2);

    // B: k-row kB (0..15), 8-float chunk c8
    const int kB = tid >> 4;
    const int c8 = (tid & 15) * 8;
    const float* b_src = We + (size_t)kB * N + n0 + c8;
    const uint32_t b16_dst = s0 + OFF_B16 + (uint32_t)((kB * SBS + c8) * 2);

    const int KT = K / BK;

    float rB[2][8];
    auto ldB = [&](int t, int slot) {
        const float* bs = b_src + (size_t)t * BK * N;
        if (ALIGN16) {
            float4 v0 = *reinterpret_cast<const float4*>(bs);
            float4 v1 = *reinterpret_cast<const float4*>(bs + 4);
            rB[slot][0] = v0.x; rB[slot][1] = v0.y; rB[slot][2] = v0.z; rB[slot][3] = v0.w;
            rB[slot][4] = v1.x; rB[slot][5] = v1.y; rB[slot][6] = v1.z; rB[slot][7] = v1.w;
        } else {
#pragma unroll
            for (int j = 0; j < 4; j++) {
                int gn = n0 + c8 + 2 * j;
                float2 v = (gn < N) ? *reinterpret_cast<const float2*>(bs + 2 * j)
                                    : make_float2(0.f, 0.f);
                rB[slot][2 * j + 0] = v.x; rB[slot][2 * j + 1] = v.y;
            }
        }
    };
    auto stsB = [&](int t, int slot) {
        sts128(b16_dst + (uint32_t)((t & 1) * B16_B),
               pack2(rB[slot][0], rB[slot][1]), pack2(rB[slot][2], rB[slot][3]),
               pack2(rB[slot][4], rB[slot][5]), pack2(rB[slot][6], rB[slot][7]));
    };
    auto issueA = [&](int t) {
        cp_async16(a16_dst + (uint32_t)((t % 5) * SA_B), a_h + (size_t)t * BK);
    };

    // warp tiling: 2 warps along M (64), 4 along N (32)
    const int wm = (warp & 1) * 64;
    const int wn = (warp >> 1) * 32;
    const int g  = lane >> 2;
    const int tg = lane & 3;

    const uint32_t a_ld0 = s0 + OFF_A16 +
        (uint32_t)(((wm + (lane & 15)) * SAS + (lane >> 4) * 8) * 2);
    const uint32_t b_ld0 = s0 + OFF_B16 +
        (uint32_t)(((lane & 15) * SBS + wn + (lane >> 4) * 8) * 2);

    float acc[4][4][4];
#pragma unroll
    for (int mi = 0; mi < 4; mi++)
#pragma unroll
        for (int ni = 0; ni < 4; ni++)
#pragma unroll
            for (int k = 0; k < 4; k++) acc[mi][ni][k] = 0.f;

    // prologue
    ldB(0, 0);
    ldB(1, 1);
    issueA(0); cp_commit();
    issueA(1); cp_commit();
    issueA(2); cp_commit();
    issueA(3); cp_commit();
    stsB(0, 0);
    cp_wait<3>();          // A(0) arrived
    __syncthreads();

    for (int t = 0; t < KT; t++) {
        // issue LDG for t+2 early (slot t&1 was consumed by stsB(t) last iter)
        if (t + 2 < KT) ldB(t + 2, t & 1);

        // ---- MMA on stage t (covers the LDG(t+1) scoreboard) ----
        const uint32_t a_ld = a_ld0 + (uint32_t)((t % 5) * SA_B);
        const uint32_t b_ld = b_ld0 + (uint32_t)((t & 1) * B16_B);
        uint32_t bf[8];
        ldsm4t(bf,     b_ld);
        ldsm4t(bf + 4, b_ld + 32);
#pragma unroll
        for (int mi = 0; mi < 4; mi++) {
            uint32_t af[4];
            ldsm4(af, a_ld + (uint32_t)(mi * 16 * SAS * 2));
            mma_f16(acc[mi][0], af, bf[0], bf[1]);
            mma_f16(acc[mi][1], af, bf[2], bf[3]);
            mma_f16(acc[mi][2], af, bf[4], bf[5]);
            mma_f16(acc[mi][3], af, bf[6], bf[7]);
        }

        // publish B(t+1) AFTER the MMA block: LDG(t+1) has had a full
        // iteration + this MMA block to complete.
        if (t + 1 < KT) stsB(t + 1, (t + 1) & 1);

        if (t + 4 < KT) issueA(t + 4);
        cp_commit();
        cp_wait<3>();      // A(t+1) arrived
        __syncthreads();
    }

    // epilogue
#pragma unroll
    for (int mi = 0; mi < 4; mi++) {
#pragma unroll
        for (int half = 0; half < 2; half++) {
            const int m = wm + mi * 16 + g + half * 8;
            const int gmm = mtile * BM + m;
            if (gmm >= cnt) continue;
            const int orow = idxE[gmm];
#pragma unroll
            for (int ni = 0; ni < 4; ni++) {
                const int gn = n0 + wn + ni * 8 + tg * 2;
                float v0 = acc[mi][ni][half * 2 + 0];
                float v1 = acc[mi][ni][half * 2 + 1];
                if (OUT_HALF) {
                    float r0 = v0 + be[gn];
                    float r1 = v1 + be[gn + 1];
                    if (DO_GELU) { r0 = gelu_exact(r0); r1 = gelu_exact(r1); }
                    *reinterpret_cast<__half2*>((__half*)Coutv +
                        (size_t)orow * ldc + gn) = __float22half2_rn(make_float2(r0, r1));
                } else {
                    float* op = (float*)Coutv + (size_t)orow * ldc;
                    if (gn + 1 < N) {
                        float r0 = v0 + be[gn];
                        float r1 = v1 + be[gn + 1];
                        if (DO_GELU) { r0 = gelu_exact(r0); r1 = gelu_exact(r1); }
                        *reinterpret_cast<float2*>(op + gn) = make_float2(r0, r1);
                    } else if (gn < N) {
                        float r0 = v0 + be[gn];
                        if (DO_GELU) r0 = gelu_exact(r0);
                        op[gn] = r0;
                    }
                }
            }
        }
    }
}

// ===========================================================================
// Kernel B (L1): fp32 A + fp32 W via 4-stage cp.async staging + smem convert.
// ===========================================================================
__global__ void __launch_bounds__(NTHREADS, 2)
expert_gemm_l1(const float* __restrict__ A, int lda,
               const float* __restrict__ W, const float* __restrict__ bias,
               __half* __restrict__ Cout, int ldc, int K, int N)
{
    const int e = blockIdx.z;
    const int cnt = g_cnt[e];
    const int mtile = blockIdx.y;
    if (mtile * BM >= cnt) return;
    const int n0 = blockIdx.x * BN;

    const int* idxE = g_idx + e * B_;
    const float* We = W + (size_t)e * K * N;
    const float* be = bias + (size_t)e * N;

    constexpr uint32_t OFF_A16 = 0;
    constexpr uint32_t OFF_ASTG = OFF_A16 + 2 * SA_B;
    constexpr uint32_t OFF_BSTG = OFF_ASTG + 4 * ASTG_B;
    constexpr uint32_t OFF_B16  = OFF_BSTG + 4 * BSTG_B;

    extern __shared__ char smem_raw[];
    const uint32_t s0 = (uint32_t)__cvta_generic_to_shared(smem_raw);

    const int tid = threadIdx.x;
    const int lane = tid & 31;
    const int warp = tid >> 5;

    const int rA = tid >> 1;
    const int ha = tid & 1;
    int gm = mtile * BM + rA;
    int gmc = gm < cnt ? gm : cnt - 1;
    const float* a_f = A + (size_t)idxE[gmc] * lda + 8 * ha;
    const uint32_t a16_dst = s0 + OFF_A16 + (uint32_t)((rA * SAS + 8 * ha) * 2);
    const uint32_t astg_dst = s0 + OFF_ASTG + (uint32_t)((rA * FAS + 8 * ha) * 4);

    const int kB = tid >> 4;
    const int c8 = (tid & 15) * 8;
    const float* b_src = We + (size_t)kB * N + n0 + c8;
    const uint32_t bstg_dst = s0 + OFF_BSTG + (uint32_t)((kB * FBS + c8) * 4);
    const uint32_t b16_dst  = s0 + OFF_B16  + (uint32_t)((kB * SBS + c8) * 2);

    const int KT = K / BK;

    auto issue = [&](int t) {
        const float* as = a_f + (size_t)t * BK;
        const uint32_t ad = astg_dst + (uint32_t)((t & 3) * ASTG_B);
        cp_async16(ad, as);
        cp_async16(ad + 16, as + 4);
        const float* bs = b_src + (size_t)t * BK * N;
        const uint32_t bd = bstg_dst + (uint32_t)((t & 3) * BSTG_B);
        cp_async16(bd, bs);
        cp_async16(bd + 16, bs + 4);
    };
    auto convert = [&](int u) {
        const uint32_t src = s0 + OFF_BSTG + (uint32_t)((u & 3) * BSTG_B)
                           + (uint32_t)((kB * FBS + c8) * 4);
        float4 v0, v1;
        lds128f(v0, src);
        lds128f(v1, src + 16);
        sts128(b16_dst + (uint32_t)((u & 1) * B16_B),
               pack2(v0.x, v0.y), pack2(v0.z, v0.w),
               pack2(v1.x, v1.y), pack2(v1.z, v1.w));
        const uint32_t asrc = s0 + OFF_ASTG + (uint32_t)((u & 3) * ASTG_B)
                            + (uint32_t)((rA * FAS + 8 * ha) * 4);
        float4 w0, w1;
        lds128f(w0, asrc);
        lds128f(w1, asrc + 16);
        sts128(a16_dst + (uint32_t)((u & 1) * SA_B),
               pack2(w0.x, w0.y), pack2(w0.z, w0.w),
               pack2(w1.x, w1.y), pack2(w1.z, w1.w));
    };

    const int wm = (warp & 1) * 64;
    const int wn = (warp >> 1) * 32;
    const int g  = lane >> 2;
    const int tg = lane & 3;

    const uint32_t a_ld0 = s0 + OFF_A16 +
        (uint32_t)(((wm + (lane & 15)) * SAS + (lane >> 4) * 8) * 2);
    const uint32_t b_ld0 = s0 + OFF_B16 +
        (uint32_t)(((lane & 15) * SBS + wn + (lane >> 4) * 8) * 2);

    float acc[4][4][4];
#pragma unroll
    for (int mi = 0; mi < 4; mi++)
#pragma unroll
        for (int ni = 0; ni < 4; ni++)
#pragma unroll
            for (int k = 0; k < 4; k++) acc[mi][ni][k] = 0.f;

    issue(0); cp_commit();
    issue(1); cp_commit();
    issue(2); cp_commit();
    cp_wait<2>();
    __syncthreads();
    convert(0);

    for (int t = 0; t < KT; t++) {
        if (t + 3 < KT) issue(t + 3);
        cp_commit();
        cp_wait<2>();
        __syncthreads();
        if (t + 1 < KT) convert(t + 1);

        const uint32_t a_ld = a_ld0 + (uint32_t)((t & 1) * SA_B);
        const uint32_t b_ld = b_ld0 + (uint32_t)((t & 1) * B16_B);
        uint32_t bf[8];
        ldsm4t(bf,     b_ld);
        ldsm4t(bf + 4, b_ld + 32);
#pragma unroll
        for (int mi = 0; mi < 4; mi++) {
            uint32_t af[4];
            ldsm4(af, a_ld + (uint32_t)(mi * 16 * SAS * 2));
            mma_f16(acc[mi][0], af, bf[0], bf[1]);
            mma_f16(acc[mi][1], af, bf[2], bf[3]);
            mma_f16(acc[mi][2], af, bf[4], bf[5]);
            mma_f16(acc[mi][3], af, bf[6], bf[7]);
        }
    }

#pragma unroll
    for (int mi = 0; mi < 4; mi++) {
#pragma unroll
        for (int half = 0; half < 2; half++) {
            const int m = wm + mi * 16 + g + half * 8;
            const int gmm = mtile * BM + m;
            if (gmm >= cnt) continue;
            const int orow = idxE[gmm];
#pragma unroll
            for (int ni = 0; ni < 4; ni++) {
                const int gn = n0 + wn + ni * 8 + tg * 2;
                float r0 = gelu_exact(acc[mi][ni][half * 2 + 0] + be[gn]);
                float r1 = gelu_exact(acc[mi][ni][half * 2 + 1] + be[gn + 1]);
                *reinterpret_cast<__half2*>(Cout + (size_t)orow * ldc + gn) =
                    __float22half2_rn(make_float2(r0, r1));
            }
        }
    }
}

// ---------------------------------------------------------------------------
__global__ void logsoftmax_kernel(float* __restrict__ out) {
    const int b = blockIdx.x;
    float* row = out + (size_t)b * C_;
    __shared__ float sred[256];
    const int tid = threadIdx.x;

    float lmax = -3.4e38f;
    for (int i = tid; i < C_; i += 256) lmax = fmaxf(lmax, row[i]);
    sred[tid] = lmax;
    __syncthreads();
    for (int s = 128; s > 0; s >>= 1) {
        if (tid < s) sred[tid] = fmaxf(sred[tid], sred[tid + s]);
        __syncthreads();
    }
    const float mx = sred[0];
    __syncthreads();

    float lsum = 0.f;
    for (int i = tid; i < C_; i += 256) lsum += expf(row[i] - mx);
    sred[tid] = lsum;
    __syncthreads();
    for (int s = 128; s > 0; s >>= 1) {
        if (tid < s) sred[tid] += sred[tid + s];
        __syncthreads();
    }
    const float lse = mx + logf(sred[0]);

    for (int i = tid; i < C_; i += 256) row[i] = row[i] - lse;
}

// ---------------------------------------------------------------------------
#define SMEM_REG (5 * SA_B + 2 * B16_B)                            // 39424
#define SMEM_L1  (2 * SA_B + 4 * ASTG_B + 4 * BSTG_B + 2 * B16_B)  // 95744

extern "C" void kernel_launch(void* const* d_in, const int* in_sizes, int n_in,
                              void* d_out, int out_size)
{
    const float* x  = (const float*)d_in[0];
    const float* mf = (const float*)d_in[1];
    const float* W1 = (const float*)d_in[2];
    const float* b1 = (const float*)d_in[3];
    const float* W2 = (const float*)d_in[4];
    const float* b2 = (const float*)d_in[5];
    const float* W3 = (const float*)d_in[6];
    const float* b3 = (const float*)d_in[7];
    float* out = (float*)d_out;

    void *h1p = nullptr, *h2p = nullptr;
    cudaGetSymbolAddress(&h1p, g_h1);
    cudaGetSymbolAddress(&h2p, g_h2);

    cudaFuncSetAttribute(expert_gemm_l1,
                         cudaFuncAttributeMaxDynamicSharedMemorySize, SMEM_L1);
    cudaFuncSetAttribute(expert_gemm_reg<true, true, true>,
                         cudaFuncAttributeMaxDynamicSharedMemorySize, SMEM_REG);
    cudaFuncSetAttribute(expert_gemm_reg<false, false, false>,
                         cudaFuncAttributeMaxDynamicSharedMemorySize, SMEM_REG);

    route_kernel<<<1, B_>>>(mf);

    // L1: x fp32 [cnt,1536] @ W1 -> gelu -> h1 (fp16)
    expert_gemm_l1<<<dim3(H_ / BN, MT, E_), NTHREADS, SMEM_L1>>>(
        x, D_, W1, b1, (__half*)h1p, H_, D_, H_);
    // L2: h1 fp16 [cnt,3072] @ W2 -> gelu -> h2 (fp16)
    expert_gemm_reg<true, true, true>
        <<<dim3(H_ / BN, MT, E_), NTHREADS, SMEM_REG>>>(
        (const __half*)h1p, H_, W2, b2, h2p, H_, H_, H_);
    // L3: h2 fp16 [cnt,3072] @ W3 + b3 -> preds (fp32)
    expert_gemm_reg<false, false, false>
        <<<dim3((C_ + BN - 1) / BN, MT, E_), NTHREADS, SMEM_REG>>>(
        (const __half*)h2p, H_, W3, b3, out, C_, H_, C_);
    logsoftmax_kernel<<<B_, 256>>>(out);
}

// round 12
// speedup vs baseline: 1.1003x; 1.1003x over previous
#include <cuda_runtime.h>
#include <cuda_fp16.h>
#include <cstdint>

#define E_ 11
#define B_ 1024
#define D_ 1536
#define H_ 3072
#define C_ 5242
#define CP_ 5248                  // padded partial stride for L3

#define BM 128
#define BN 128
#define BK 16
#define NTHREADS 256
#define MT 2                      // m-tiles per bin (safety for cnt>128)
#define NSPLIT 2                  // K splits

#define SAS 24                    // A fp16 tile stride (halves)
#define SA_B (BM * SAS * 2)       // 6144 B per A fp16 stage
#define FAS 20                    // A fp32 staging stride (floats) [L1 kernel]
#define ASTG_B (BM * FAS * 4)     // 10240 B per A fp32 stage
#define FBS 132                   // B fp32 staging stride (floats) [L1 kernel]
#define BSTG_B (BK * FBS * 4)     // 8448 B per B fp32 stage
#define SBS 136                   // B fp16 tile stride (halves)
#define B16_B (BK * SBS * 2)      // 4352 B per B fp16 tile

// ---- scratch (device globals: no allocations allowed) ----
__device__ int    g_cnt[E_];
__device__ int    g_idx[E_ * B_];
__device__ int    g_bin[B_];
__device__ __half g_h1[(size_t)B_ * H_];
__device__ __half g_h2[(size_t)B_ * H_];
__device__ float  g_p0[(size_t)B_ * CP_];
__device__ float  g_p1[(size_t)B_ * CP_];

// ---------------------------------------------------------------------------
__global__ void route_kernel(const float* __restrict__ mf) {
    int tid = threadIdx.x;
    if (tid < E_) g_cnt[tid] = 0;
    __syncthreads();
    float t = 1.0f - mf[tid];
    float q = t / 0.1f;               // IEEE div, matches XLA lowering
    int bin = (int)q;                 // trunc toward zero == astype(int32)
    bin = max(0, min(E_ - 1, bin));
    g_bin[tid] = bin;
    int pos = atomicAdd(&g_cnt[bin], 1);
    g_idx[bin * B_ + pos] = tid;
}

// ---- PTX helpers ----------------------------------------------------------
__device__ __forceinline__ void cp_async16(uint32_t s, const void* g) {
    asm volatile("cp.async.cg.shared.global [%0], [%1], 16;\n" :: "r"(s), "l"(g));
}
__device__ __forceinline__ void cp_commit() {
    asm volatile("cp.async.commit_group;\n" ::: "memory");
}
template <int N>
__device__ __forceinline__ void cp_wait() {
    asm volatile("cp.async.wait_group %0;\n" :: "n"(N) : "memory");
}
__device__ __forceinline__ void ldsm4(uint32_t r[4], uint32_t addr) {
    asm volatile("ldmatrix.sync.aligned.m8n8.x4.shared.b16 {%0,%1,%2,%3}, [%4];"
                 : "=r"(r[0]), "=r"(r[1]), "=r"(r[2]), "=r"(r[3]) : "r"(addr));
}
__device__ __forceinline__ void ldsm4t(uint32_t r[4], uint32_t addr) {
    asm volatile("ldmatrix.sync.aligned.m8n8.x4.trans.shared.b16 {%0,%1,%2,%3}, [%4];"
                 : "=r"(r[0]), "=r"(r[1]), "=r"(r[2]), "=r"(r[3]) : "r"(addr));
}
__device__ __forceinline__ void mma_f16(float c[4], const uint32_t a[4],
                                        const uint32_t b0, const uint32_t b1) {
    asm volatile(
        "mma.sync.aligned.m16n8k16.row.col.f32.f16.f16.f32 "
        "{%0,%1,%2,%3}, {%4,%5,%6,%7}, {%8,%9}, {%0,%1,%2,%3};\n"
        : "+f"(c[0]), "+f"(c[1]), "+f"(c[2]), "+f"(c[3])
        : "r"(a[0]), "r"(a[1]), "r"(a[2]), "r"(a[3]), "r"(b0), "r"(b1));
}
__device__ __forceinline__ void lds128f(float4& v, uint32_t a) {
    asm volatile("ld.shared.v4.f32 {%0,%1,%2,%3}, [%4];"
                 : "=f"(v.x), "=f"(v.y), "=f"(v.z), "=f"(v.w) : "r"(a));
}
__device__ __forceinline__ void sts128(uint32_t a, uint32_t v0, uint32_t v1,
                                       uint32_t v2, uint32_t v3) {
    asm volatile("st.shared.v4.b32 [%0], {%1,%2,%3,%4};\n"
                 :: "r"(a), "r"(v0), "r"(v1), "r"(v2), "r"(v3));
}
__device__ __forceinline__ uint32_t pack2(float x, float y) {
    __half2 h = __float22half2_rn(make_float2(x, y));
    return *reinterpret_cast<uint32_t*>(&h);
}
__device__ __forceinline__ float gelu_exact(float x) {
    return 0.5f * x * (1.0f + erff(x * 0.70710678118654752f));
}

// ===========================================================================
// Split-K gather GEMM (fp16 A): writes raw fp32 partials (no bias/act).
// blockIdx.y = split*MT + mtile. CTA 128x128, 8 warps (64x32), 2 CTAs/SM.
// ===========================================================================
template <bool ALIGN16>
__global__ void __launch_bounds__(NTHREADS, 2)
gemm_split(const __half* __restrict__ A, int lda,
           const float* __restrict__ W,
           float* __restrict__ P0, float* __restrict__ P1, int ldp,
           int KSPL, int N)
{
    const int e = blockIdx.z;
    const int cnt = g_cnt[e];
    const int mtile = blockIdx.y % MT;
    const int split = blockIdx.y / MT;
    if (mtile * BM >= cnt) return;
    const int n0 = blockIdx.x * BN;

    const int* idxE = g_idx + e * B_;
    const float* We = W + (size_t)e * (size_t)(KSPL * NSPLIT) * N
                        + (size_t)split * KSPL * N;
    float* Pout = split == 0 ? P0 : P1;

    constexpr uint32_t OFF_A16 = 0;                 // 5 stages
    constexpr uint32_t OFF_B16 = 5 * SA_B;          // 2 tiles

    extern __shared__ char smem_raw[];
    const uint32_t s0 = (uint32_t)__cvta_generic_to_shared(smem_raw);

    const int tid = threadIdx.x;
    const int lane = tid & 31;
    const int warp = tid >> 5;

    // A: one gathered row per thread-pair
    const int rA = tid >> 1;
    const int ha = tid & 1;
    int gm = mtile * BM + rA;
    int gmc = gm < cnt ? gm : cnt - 1;
    const __half* a_h = A + (size_t)idxE[gmc] * lda + split * KSPL + 8 * ha;
    const uint32_t a16_dst = s0 + OFF_A16 + (uint32_t)((rA * SAS + 8 * ha) * 2);

    // B: k-row kB (0..15), 8-float chunk c8
    const int kB = tid >> 4;
    const int c8 = (tid & 15) * 8;
    const float* b_src = We + (size_t)kB * N + n0 + c8;
    const uint32_t b16_dst = s0 + OFF_B16 + (uint32_t)((kB * SBS + c8) * 2);

    const int KT = KSPL / BK;

    float rB[2][8];
    auto ldB = [&](int t, int slot) {
        const float* bs = b_src + (size_t)t * BK * N;
        if (ALIGN16) {
            float4 v0 = *reinterpret_cast<const float4*>(bs);
            float4 v1 = *reinterpret_cast<const float4*>(bs + 4);
            rB[slot][0] = v0.x; rB[slot][1] = v0.y; rB[slot][2] = v0.z; rB[slot][3] = v0.w;
            rB[slot][4] = v1.x; rB[slot][5] = v1.y; rB[slot][6] = v1.z; rB[slot][7] = v1.w;
        } else {
#pragma unroll
            for (int j = 0; j < 4; j++) {
                int gn = n0 + c8 + 2 * j;
                float2 v = (gn < N) ? *reinterpret_cast<const float2*>(bs + 2 * j)
                                    : make_float2(0.f, 0.f);
                rB[slot][2 * j + 0] = v.x; rB[slot][2 * j + 1] = v.y;
            }
        }
    };
    auto stsB = [&](int t, int slot) {
        sts128(b16_dst + (uint32_t)((t & 1) * B16_B),
               pack2(rB[slot][0], rB[slot][1]), pack2(rB[slot][2], rB[slot][3]),
               pack2(rB[slot][4], rB[slot][5]), pack2(rB[slot][6], rB[slot][7]));
    };
    auto issueA = [&](int t) {
        cp_async16(a16_dst + (uint32_t)((t % 5) * SA_B), a_h + (size_t)t * BK);
    };

    // warp tiling: 2 warps along M (64), 4 along N (32)
    const int wm = (warp & 1) * 64;
    const int wn = (warp >> 1) * 32;
    const int g  = lane >> 2;
    const int tg = lane & 3;

    const uint32_t a_ld0 = s0 + OFF_A16 +
        (uint32_t)(((wm + (lane & 15)) * SAS + (lane >> 4) * 8) * 2);
    const uint32_t b_ld0 = s0 + OFF_B16 +
        (uint32_t)(((lane & 15) * SBS + wn + (lane >> 4) * 8) * 2);

    float acc[4][4][4];
#pragma unroll
    for (int mi = 0; mi < 4; mi++)
#pragma unroll
        for (int ni = 0; ni < 4; ni++)
#pragma unroll
            for (int k = 0; k < 4; k++) acc[mi][ni][k] = 0.f;

    // prologue
    ldB(0, 0);
    ldB(1, 1);
    issueA(0); cp_commit();
    issueA(1); cp_commit();
    issueA(2); cp_commit();
    issueA(3); cp_commit();
    stsB(0, 0);
    cp_wait<3>();
    __syncthreads();

    for (int t = 0; t < KT; t++) {
        if (t + 2 < KT) ldB(t + 2, t & 1);

        const uint32_t a_ld = a_ld0 + (uint32_t)((t % 5) * SA_B);
        const uint32_t b_ld = b_ld0 + (uint32_t)((t & 1) * B16_B);
        uint32_t bf[8];
        ldsm4t(bf,     b_ld);
        ldsm4t(bf + 4, b_ld + 32);
#pragma unroll
        for (int mi = 0; mi < 4; mi++) {
            uint32_t af[4];
            ldsm4(af, a_ld + (uint32_t)(mi * 16 * SAS * 2));
            mma_f16(acc[mi][0], af, bf[0], bf[1]);
            mma_f16(acc[mi][1], af, bf[2], bf[3]);
            mma_f16(acc[mi][2], af, bf[4], bf[5]);
            mma_f16(acc[mi][3], af, bf[6], bf[7]);
        }

        if (t + 1 < KT) stsB(t + 1, (t + 1) & 1);

        if (t + 4 < KT) issueA(t + 4);
        cp_commit();
        cp_wait<3>();
        __syncthreads();
    }

    // epilogue: raw partial store
#pragma unroll
    for (int mi = 0; mi < 4; mi++) {
#pragma unroll
        for (int half = 0; half < 2; half++) {
            const int m = wm + mi * 16 + g + half * 8;
            const int gmm = mtile * BM + m;
            if (gmm >= cnt) continue;
            float* op = Pout + (size_t)idxE[gmm] * ldp;
#pragma unroll
            for (int ni = 0; ni < 4; ni++) {
                const int gn = n0 + wn + ni * 8 + tg * 2;
                if (gn + 1 < N) {
                    *reinterpret_cast<float2*>(op + gn) =
                        make_float2(acc[mi][ni][half * 2 + 0],
                                    acc[mi][ni][half * 2 + 1]);
                } else if (gn < N) {
                    op[gn] = acc[mi][ni][half * 2 + 0];
                }
            }
        }
    }
}

// ===========================================================================
// L1 split-K GEMM (fp32 A + fp32 W via staging+convert). Partial out.
// ===========================================================================
__global__ void __launch_bounds__(NTHREADS, 2)
gemm_l1_split(const float* __restrict__ A, int lda,
              const float* __restrict__ W,
              float* __restrict__ P0, float* __restrict__ P1, int ldp,
              int KSPL, int N)
{
    const int e = blockIdx.z;
    const int cnt = g_cnt[e];
    const int mtile = blockIdx.y % MT;
    const int split = blockIdx.y / MT;
    if (mtile * BM >= cnt) return;
    const int n0 = blockIdx.x * BN;

    const int* idxE = g_idx + e * B_;
    const float* We = W + (size_t)e * (size_t)(KSPL * NSPLIT) * N
                        + (size_t)split * KSPL * N;
    float* Pout = split == 0 ? P0 : P1;

    constexpr uint32_t OFF_A16 = 0;
    constexpr uint32_t OFF_ASTG = OFF_A16 + 2 * SA_B;
    constexpr uint32_t OFF_BSTG = OFF_ASTG + 4 * ASTG_B;
    constexpr uint32_t OFF_B16  = OFF_BSTG + 4 * BSTG_B;

    extern __shared__ char smem_raw[];
    const uint32_t s0 = (uint32_t)__cvta_generic_to_shared(smem_raw);

    const int tid = threadIdx.x;
    const int lane = tid & 31;
    const int warp = tid >> 5;

    const int rA = tid >> 1;
    const int ha = tid & 1;
    int gm = mtile * BM + rA;
    int gmc = gm < cnt ? gm : cnt - 1;
    const float* a_f = A + (size_t)idxE[gmc] * lda + split * KSPL + 8 * ha;
    const uint32_t a16_dst = s0 + OFF_A16 + (uint32_t)((rA * SAS + 8 * ha) * 2);
    const uint32_t astg_dst = s0 + OFF_ASTG + (uint32_t)((rA * FAS + 8 * ha) * 4);

    const int kB = tid >> 4;
    const int c8 = (tid & 15) * 8;
    const float* b_src = We + (size_t)kB * N + n0 + c8;
    const uint32_t bstg_dst = s0 + OFF_BSTG + (uint32_t)((kB * FBS + c8) * 4);
    const uint32_t b16_dst  = s0 + OFF_B16  + (uint32_t)((kB * SBS + c8) * 2);

    const int KT = KSPL / BK;

    auto issue = [&](int t) {
        const float* as = a_f + (size_t)t * BK;
        const uint32_t ad = astg_dst + (uint32_t)((t & 3) * ASTG_B);
        cp_async16(ad, as);
        cp_async16(ad + 16, as + 4);
        const float* bs = b_src + (size_t)t * BK * N;
        const uint32_t bd = bstg_dst + (uint32_t)((t & 3) * BSTG_B);
        cp_async16(bd, bs);
        cp_async16(bd + 16, bs + 4);
    };
    auto convert = [&](int u) {
        const uint32_t src = s0 + OFF_BSTG + (uint32_t)((u & 3) * BSTG_B)
                           + (uint32_t)((kB * FBS + c8) * 4);
        float4 v0, v1;
        lds128f(v0, src);
        lds128f(v1, src + 16);
        sts128(b16_dst + (uint32_t)((u & 1) * B16_B),
               pack2(v0.x, v0.y), pack2(v0.z, v0.w),
               pack2(v1.x, v1.y), pack2(v1.z, v1.w));
        const uint32_t asrc = s0 + OFF_ASTG + (uint32_t)((u & 3) * ASTG_B)
                            + (uint32_t)((rA * FAS + 8 * ha) * 4);
        float4 w0, w1;
        lds128f(w0, asrc);
        lds128f(w1, asrc + 16);
        sts128(a16_dst + (uint32_t)((u & 1) * SA_B),
               pack2(w0.x, w0.y), pack2(w0.z, w0.w),
               pack2(w1.x, w1.y), pack2(w1.z, w1.w));
    };

    const int wm = (warp & 1) * 64;
    const int wn = (warp >> 1) * 32;
    const int g  = lane >> 2;
    const int tg = lane & 3;

    const uint32_t a_ld0 = s0 + OFF_A16 +
        (uint32_t)(((wm + (lane & 15)) * SAS + (lane >> 4) * 8) * 2);
    const uint32_t b_ld0 = s0 + OFF_B16 +
        (uint32_t)(((lane & 15) * SBS + wn + (lane >> 4) * 8) * 2);

    float acc[4][4][4];
#pragma unroll
    for (int mi = 0; mi < 4; mi++)
#pragma unroll
        for (int ni = 0; ni < 4; ni++)
#pragma unroll
            for (int k = 0; k < 4; k++) acc[mi][ni][k] = 0.f;

    issue(0); cp_commit();
    issue(1); cp_commit();
    issue(2); cp_commit();
    cp_wait<2>();
    __syncthreads();
    convert(0);

    for (int t = 0; t < KT; t++) {
        if (t + 3 < KT) issue(t + 3);
        cp_commit();
        cp_wait<2>();
        __syncthreads();
        if (t + 1 < KT) convert(t + 1);

        const uint32_t a_ld = a_ld0 + (uint32_t)((t & 1) * SA_B);
        const uint32_t b_ld = b_ld0 + (uint32_t)((t & 1) * B16_B);
        uint32_t bf[8];
        ldsm4t(bf,     b_ld);
        ldsm4t(bf + 4, b_ld + 32);
#pragma unroll
        for (int mi = 0; mi < 4; mi++) {
            uint32_t af[4];
            ldsm4(af, a_ld + (uint32_t)(mi * 16 * SAS * 2));
            mma_f16(acc[mi][0], af, bf[0], bf[1]);
            mma_f16(acc[mi][1], af, bf[2], bf[3]);
            mma_f16(acc[mi][2], af, bf[4], bf[5]);
            mma_f16(acc[mi][3], af, bf[6], bf[7]);
        }
    }

#pragma unroll
    for (int mi = 0; mi < 4; mi++) {
#pragma unroll
        for (int half = 0; half < 2; half++) {
            const int m = wm + mi * 16 + g + half * 8;
            const int gmm = mtile * BM + m;
            if (gmm >= cnt) continue;
            float* op = Pout + (size_t)idxE[gmm] * ldp;
#pragma unroll
            for (int ni = 0; ni < 4; ni++) {
                const int gn = n0 + wn + ni * 8 + tg * 2;
                *reinterpret_cast<float2*>(op + gn) =
                    make_float2(acc[mi][ni][half * 2 + 0],
                                acc[mi][ni][half * 2 + 1]);
            }
        }
    }
}

// ===========================================================================
// Combine p0+p1+bias -> gelu -> fp16 (for h1 / h2)
// ===========================================================================
__global__ void combine_gelu(const float* __restrict__ P0,
                             const float* __restrict__ P1,
                             const float* __restrict__ bias,
                             __half* __restrict__ dst, int Ncols)
{
    const int r = blockIdx.x;
    const int e = g_bin[r];
    const float* p0 = P0 + (size_t)r * Ncols;
    const float* p1 = P1 + (size_t)r * Ncols;
    const float* be = bias + (size_t)e * Ncols;
    __half* d = dst + (size_t)r * Ncols;
    for (int i = threadIdx.x * 2; i < Ncols; i += 512) {
        float2 a = *reinterpret_cast<const float2*>(p0 + i);
        float2 b = *reinterpret_cast<const float2*>(p1 + i);
        float2 c = *reinterpret_cast<const float2*>(be + i);
        float r0 = gelu_exact(a.x + b.x + c.x);
        float r1 = gelu_exact(a.y + b.y + c.y);
        *reinterpret_cast<__half2*>(d + i) = __float22half2_rn(make_float2(r0, r1));
    }
}

// ===========================================================================
// Fused L3 combine + log_softmax: row = p0+p1+b3, cached in smem.
// ===========================================================================
__global__ void logsoftmax_combine(const float* __restrict__ P0,
                                   const float* __restrict__ P1,
                                   const float* __restrict__ b3,
                                   float* __restrict__ out)
{
    const int r = blockIdx.x;
    const int e = g_bin[r];
    const float* p0 = P0 + (size_t)r * CP_;
    const float* p1 = P1 + (size_t)r * CP_;
    const float* be = b3 + (size_t)e * C_;
    float* orow = out + (size_t)r * C_;

    __shared__ float srow[C_];
    __shared__ float sred[256];
    const int tid = threadIdx.x;

    float lmax = -3.4e38f;
    for (int i = tid; i < C_; i += 256) {
        float v = p0[i] + p1[i] + be[i];
        srow[i] = v;
        lmax = fmaxf(lmax, v);
    }
    sred[tid] = lmax;
    __syncthreads();
    for (int s = 128; s > 0; s >>= 1) {
        if (tid < s) sred[tid] = fmaxf(sred[tid], sred[tid + s]);
        __syncthreads();
    }
    const float mx = sred[0];
    __syncthreads();

    float lsum = 0.f;
    for (int i = tid; i < C_; i += 256) lsum += expf(srow[i] - mx);
    sred[tid] = lsum;
    __syncthreads();
    for (int s = 128; s > 0; s >>= 1) {
        if (tid < s) sred[tid] += sred[tid + s];
        __syncthreads();
    }
    const float lse = mx + logf(sred[0]);

    for (int i = tid; i < C_; i += 256) orow[i] = srow[i] - lse;
}

// ---------------------------------------------------------------------------
#define SMEM_REG (5 * SA_B + 2 * B16_B)                            // 39424
#define SMEM_L1  (2 * SA_B + 4 * ASTG_B + 4 * BSTG_B + 2 * B16_B)  // 95744

extern "C" void kernel_launch(void* const* d_in, const int* in_sizes, int n_in,
                              void* d_out, int out_size)
{
    const float* x  = (const float*)d_in[0];
    const float* mf = (const float*)d_in[1];
    const float* W1 = (const float*)d_in[2];
    const float* b1 = (const float*)d_in[3];
    const float* W2 = (const float*)d_in[4];
    const float* b2 = (const float*)d_in[5];
    const float* W3 = (const float*)d_in[6];
    const float* b3 = (const float*)d_in[7];
    float* out = (float*)d_out;

    void *h1p = nullptr, *h2p = nullptr, *p0p = nullptr, *p1p = nullptr;
    cudaGetSymbolAddress(&h1p, g_h1);
    cudaGetSymbolAddress(&h2p, g_h2);
    cudaGetSymbolAddress(&p0p, g_p0);
    cudaGetSymbolAddress(&p1p, g_p1);
    __half* h1 = (__half*)h1p;
    __half* h2 = (__half*)h2p;
    float* p0 = (float*)p0p;
    float* p1 = (float*)p1p;

    cudaFuncSetAttribute(gemm_l1_split,
                         cudaFuncAttributeMaxDynamicSharedMemorySize, SMEM_L1);
    cudaFuncSetAttribute(gemm_split<true>,
                         cudaFuncAttributeMaxDynamicSharedMemorySize, SMEM_REG);
    cudaFuncSetAttribute(gemm_split<false>,
                         cudaFuncAttributeMaxDynamicSharedMemorySize, SMEM_REG);

    route_kernel<<<1, B_>>>(mf);

    // L1: x fp32 [cnt,1536] @ W1 (split-K 2) -> partials -> gelu -> h1 fp16
    gemm_l1_split<<<dim3(H_ / BN, MT * NSPLIT, E_), NTHREADS, SMEM_L1>>>(
        x, D_, W1, p0, p1, H_, D_ / NSPLIT, H_);
    combine_gelu<<<B_, 256>>>(p0, p1, b1, h1, H_);

    // L2: h1 fp16 [cnt,3072] @ W2 (split-K 2) -> partials -> gelu -> h2 fp16
    gemm_split<true><<<dim3(H_ / BN, MT * NSPLIT, E_), NTHREADS, SMEM_REG>>>(
        h1, H_, W2, p0, p1, H_, H_ / NSPLIT, H_);
    combine_gelu<<<B_, 256>>>(p0, p1, b2, h2, H_);

    // L3: h2 fp16 [cnt,3072] @ W3 (split-K 2) -> partials
    gemm_split<false><<<dim3((C_ + BN - 1) / BN, MT * NSPLIT, E_), NTHREADS, SMEM_REG>>>(
        h2, H_, W3, p0, p1, CP_, H_ / NSPLIT, C_);
    // combine + bias + log_softmax -> out
    logsoftmax_combine<<<B_, 256>>>(p0, p1, b3, out);
}